// round 2
// baseline (speedup 1.0000x reference)
#include <cuda_runtime.h>
#include <cuda_bf16.h>
#include <cstdint>
#include <math.h>

#define DIMX  1024
#define GQ    256
#define QKD   128
#define HIDX  2048
#define NTOK  16384
#define NBG   64

// ---------------- scratch (device globals; no allocation) ----------------
__device__ float g_normed[(size_t)NTOK * DIMX];
__device__ float g_v    [(size_t)NTOK * HIDX];
__device__ float g_gate [(size_t)NTOK * HIDX];
__device__ float g_qksilu[(size_t)NTOK * QKD];
__device__ float g_qq   [(size_t)NTOK * QKD];
__device__ float g_lq   [(size_t)NTOK * QKD];
__device__ float g_qkT  [(size_t)NBG * QKD * GQ];
__device__ float g_lkT  [(size_t)NBG * QKD * GQ];
__device__ float g_attn [(size_t)NBG * GQ * GQ];
__device__ float g_linkv[(size_t)NBG * QKD * HIDX];
__device__ float g_linkvc[(size_t)NBG * QKD * HIDX];
__device__ float g_act  [(size_t)NTOK * HIDX];
__device__ float g_biastab[GQ];

// ---------------- small helpers ----------------
__device__ __forceinline__ float silu_f(float x) { return x / (1.0f + expf(-x)); }

__device__ __forceinline__ uint32_t f2tf(float f) {
    uint32_t r;
    asm("cvt.rna.tf32.f32 %0, %1;" : "=r"(r) : "f"(f));
    return r;
}
__device__ __forceinline__ void mma_tf32(float (&d)[4], const uint32_t (&a)[4],
                                         uint32_t b0, uint32_t b1) {
    asm volatile(
        "mma.sync.aligned.m16n8k8.row.col.f32.tf32.tf32.f32 "
        "{%0,%1,%2,%3}, {%4,%5,%6,%7}, {%8,%9}, {%0,%1,%2,%3};\n"
        : "+f"(d[0]), "+f"(d[1]), "+f"(d[2]), "+f"(d[3])
        : "r"(a[0]), "r"(a[1]), "r"(a[2]), "r"(a[3]), "r"(b0), "r"(b1));
}

// ---------------- prep: T5 bias table ----------------
__global__ void prep_kernel(const float* __restrict__ rel_table) {
    int n = threadIdx.x;   // causal distance 0..255
    int bucket;
    if (n < 16) bucket = n;
    else {
        int v = 16 + (int)(logf((float)n / 16.0f) / logf(8.0f) * 16.0f);
        bucket = v < 31 ? v : 31;
    }
    g_biastab[n] = rel_table[bucket] * sqrtf(128.0f);
}

// ---------------- LayerNorm -> fp32 ----------------
__global__ void ln_kernel(const float* __restrict__ x, const float* __restrict__ w,
                          const float* __restrict__ b) {
    int row = blockIdx.x, t = threadIdx.x;   // 256 threads, 4 floats each
    float4 f = reinterpret_cast<const float4*>(x + (size_t)row * DIMX)[t];
    float s  = f.x + f.y + f.z + f.w;
    float s2 = f.x*f.x + f.y*f.y + f.z*f.z + f.w*f.w;
    #pragma unroll
    for (int o = 16; o; o >>= 1) {
        s  += __shfl_xor_sync(0xffffffffu, s,  o);
        s2 += __shfl_xor_sync(0xffffffffu, s2, o);
    }
    __shared__ float ss[8], ss2[8], smu, sinv;
    if ((t & 31) == 0) { ss[t >> 5] = s; ss2[t >> 5] = s2; }
    __syncthreads();
    if (t == 0) {
        float S = 0.f, S2 = 0.f;
        #pragma unroll
        for (int k = 0; k < 8; k++) { S += ss[k]; S2 += ss2[k]; }
        float mu  = S * (1.0f / 1024.0f);
        float var = S2 * (1.0f / 1024.0f) - mu * mu;
        smu = mu; sinv = rsqrtf(var + 1e-5f);
    }
    __syncthreads();
    float mu = smu, inv = sinv;
    float4 wv = reinterpret_cast<const float4*>(w)[t];
    float4 bv = reinterpret_cast<const float4*>(b)[t];
    float4 o;
    o.x = (f.x - mu)*inv*wv.x + bv.x;
    o.y = (f.y - mu)*inv*wv.y + bv.y;
    o.z = (f.z - mu)*inv*wv.z + bv.z;
    o.w = (f.w - mu)*inv*wv.w + bv.w;
    reinterpret_cast<float4*>(g_normed + (size_t)row * DIMX)[t] = o;
}

// ---------------- head expand: qk_silu -> 4 heads (k heads transposed per group) ---
__global__ void qkhead_kernel(const float* __restrict__ qk_w, const float* __restrict__ qk_b) {
    int t = blockIdx.x;        // token
    int d = threadIdx.x;       // 0..127
    float v = g_qksilu[(size_t)t * QKD + d];
    int bg = t >> 8, nl = t & 255;
    g_qq[(size_t)t * QKD + d] = v * qk_w[d]         + qk_b[d];
    g_lq[(size_t)t * QKD + d] = v * qk_w[QKD + d]   + qk_b[QKD + d];
    g_qkT[(size_t)bg * QKD * GQ + (size_t)d * GQ + nl] = v * qk_w[2*QKD + d] + qk_b[2*QKD + d];
    g_lkT[(size_t)bg * QKD * GQ + (size_t)d * GQ + nl] = v * qk_w[3*QKD + d] + qk_b[3*QKD + d];
}

// ---------------- exclusive cumsum over groups (fp32) ----------------
__global__ void cumsum_kernel() {
    int i  = blockIdx.x * 256 + threadIdx.x;     // < 4*2^18
    int b  = i >> 18;
    int de = i & ((1 << 18) - 1);                // 128*2048 = 2^18
    float a = 0.f;
    #pragma unroll
    for (int g = 0; g < 16; g++) {
        size_t off = ((size_t)(b * 16 + g) << 18) + de;
        g_linkvc[off] = a;
        a += g_linkv[off];
    }
}

// ---------------- generic tf32 MMA GEMM, 128x128x32 tile, 6 modes ----------------
// MODE 0: normed@Wh  +bh, silu, split v/gate      M=16384 N=4096 K=1024
// MODE 1: normed@Wqk +bqk, silu -> qksilu         M=16384 N=128  K=1024
// MODE 2: sim = qq@qkT /256 +bias, relu^2, mask   M=256b  N=256  K=128
// MODE 3: linkv = lkT@v /256                      M=128b  N=2048 K=256
// MODE 4: [attn|lq]@[v;linkvc], * gate -> act     M=256b  N=2048 K=384
// MODE 5: act@Wout +bout +x -> out                M=16384 N=1024 K=2048
constexpr int KDIM[6] = {1024, 1024, 128, 256, 384, 2048};

#define ASTRIDE 36
#define BSTRIDE 132
#define A_BUF   (128 * ASTRIDE)
#define B_BUF   (32 * BSTRIDE)
#define SMEM_BYTES ((2 * A_BUF + 2 * B_BUF) * 4)

template<int MODE>
__device__ __forceinline__ const float* a_ptr(int bg, int m, int k) {
    if constexpr (MODE == 0 || MODE == 1) return g_normed + (size_t)m * DIMX + k;
    else if constexpr (MODE == 2) return g_qq + ((size_t)bg * GQ + m) * QKD + k;
    else if constexpr (MODE == 3) return g_lkT + (size_t)bg * QKD * GQ + (size_t)m * GQ + k;
    else if constexpr (MODE == 4) {
        if (k < GQ) return g_attn + (size_t)bg * GQ * GQ + (size_t)m * GQ + k;
        else        return g_lq + ((size_t)bg * GQ + m) * QKD + (k - GQ);
    }
    else return g_act + (size_t)m * HIDX + k;
}
template<int MODE>
__device__ __forceinline__ const float* b_ptr(const float* Bw, int bg, int k, int n) {
    if constexpr (MODE == 0) return Bw + (size_t)k * (2 * HIDX) + n;
    else if constexpr (MODE == 1) return Bw + (size_t)k * QKD + n;
    else if constexpr (MODE == 2) return g_qkT + (size_t)bg * QKD * GQ + (size_t)k * GQ + n;
    else if constexpr (MODE == 3) return g_v + ((size_t)bg * GQ + k) * HIDX + n;
    else if constexpr (MODE == 4) {
        if (k < GQ) return g_v + ((size_t)bg * GQ + k) * HIDX + n;
        else        return g_linkvc + (size_t)bg * QKD * HIDX + (size_t)(k - GQ) * HIDX + n;
    }
    else return Bw + (size_t)k * DIMX + n;
}

template<int MODE>
__global__ void __launch_bounds__(256) gemm_kernel(const float* __restrict__ Bw,
                                                   const float* __restrict__ bias,
                                                   const float* __restrict__ xres,
                                                   float* __restrict__ out) {
    constexpr int K  = KDIM[MODE];
    constexpr int KT = K / 32;
    extern __shared__ float smem[];
    float* As = smem;                 // [2][128][ASTRIDE]
    float* Bs = smem + 2 * A_BUF;     // [2][32][BSTRIDE]

    const int tid = threadIdx.x;
    const int m0 = blockIdx.x * 128;
    const int n0 = blockIdx.y * 128;
    const int bg = blockIdx.z;
    const int warp = tid >> 5, lane = tid & 31;
    const int wm = warp & 3, wn = warp >> 2;           // 4x2 warps -> 32x64 each
    const int gid = lane >> 2, tig = lane & 3;         // fragment addressing
    const int lm = lane >> 2, ln = (lane & 3) << 1;    // C-fragment addressing

    uint32_t sA = (uint32_t)__cvta_generic_to_shared(As);
    uint32_t sB = (uint32_t)__cvta_generic_to_shared(Bs);

    float acc[2][8][4];
    #pragma unroll
    for (int a = 0; a < 2; a++)
        #pragma unroll
        for (int b = 0; b < 8; b++)
            #pragma unroll
            for (int c = 0; c < 4; c++) acc[a][b][c] = 0.f;

    auto load_tile = [&](int kt, int buf) {
        int k0 = kt * 32;
        #pragma unroll
        for (int it = 0; it < 4; it++) {                    // A: 128x32 fp32, 16B chunks
            int idx = tid + it * 256;
            int r = idx >> 3, kc = (idx & 7) << 2;
            const float* gp = a_ptr<MODE>(bg, m0 + r, k0 + kc);
            uint32_t sa = sA + ((buf * 128 + r) * ASTRIDE + kc) * 4;
            asm volatile("cp.async.cg.shared.global [%0], [%1], 16;\n" :: "r"(sa), "l"(gp));
        }
        #pragma unroll
        for (int it = 0; it < 4; it++) {                    // B: 32x128 fp32
            int idx = tid + it * 256;
            int r = idx >> 5, nc = (idx & 31) << 2;
            const float* gp = b_ptr<MODE>(Bw, bg, k0 + r, n0 + nc);
            uint32_t sb = sB + ((buf * 32 + r) * BSTRIDE + nc) * 4;
            asm volatile("cp.async.cg.shared.global [%0], [%1], 16;\n" :: "r"(sb), "l"(gp));
        }
        asm volatile("cp.async.commit_group;\n");
    };

    load_tile(0, 0);
    for (int kt = 0; kt < KT; kt++) {
        int cur = kt & 1;
        if (kt + 1 < KT) {
            load_tile(kt + 1, cur ^ 1);
            asm volatile("cp.async.wait_group 1;\n");
        } else {
            asm volatile("cp.async.wait_group 0;\n");
        }
        __syncthreads();
        #pragma unroll
        for (int ks = 0; ks < 32; ks += 8) {
            uint32_t af[2][4], bfr[8][2];
            #pragma unroll
            for (int mf = 0; mf < 2; mf++) {
                const float* ab = As + (cur * 128 + wm * 32 + mf * 16 + gid) * ASTRIDE + ks + tig;
                af[mf][0] = f2tf(ab[0]);
                af[mf][1] = f2tf(ab[8 * ASTRIDE]);
                af[mf][2] = f2tf(ab[4]);
                af[mf][3] = f2tf(ab[8 * ASTRIDE + 4]);
            }
            #pragma unroll
            for (int nt = 0; nt < 8; nt++) {
                const float* bb = Bs + (cur * 32 + ks + tig) * BSTRIDE + wn * 64 + nt * 8 + gid;
                bfr[nt][0] = f2tf(bb[0]);
                bfr[nt][1] = f2tf(bb[4 * BSTRIDE]);
            }
            #pragma unroll
            for (int mf = 0; mf < 2; mf++)
                #pragma unroll
                for (int nf = 0; nf < 8; nf++)
                    mma_tf32(acc[mf][nf], af[mf], bfr[nf][0], bfr[nf][1]);
        }
        __syncthreads();
    }

    // -------- epilogue --------
    #pragma unroll
    for (int mf = 0; mf < 2; mf++)
    #pragma unroll
    for (int nf = 0; nf < 8; nf++)
    #pragma unroll
    for (int h = 0; h < 2; h++) {
        int m = m0 + wm * 32 + mf * 16 + lm + h * 8;
        int n = n0 + wn * 64 + nf * 8 + ln;
        float v0 = acc[mf][nf][h * 2 + 0];
        float v1 = acc[mf][nf][h * 2 + 1];
        if constexpr (MODE == 0) {
            float h0 = silu_f(v0 + bias[n]);
            float h1 = silu_f(v1 + bias[n + 1]);
            if (n < HIDX)
                *reinterpret_cast<float2*>(g_v + (size_t)m * HIDX + n) = make_float2(h0, h1);
            else
                *reinterpret_cast<float2*>(g_gate + (size_t)m * HIDX + (n - HIDX)) = make_float2(h0, h1);
        } else if constexpr (MODE == 1) {
            float h0 = silu_f(v0 + bias[n]);
            float h1 = silu_f(v1 + bias[n + 1]);
            *reinterpret_cast<float2*>(g_qksilu + (size_t)m * QKD + n) = make_float2(h0, h1);
        } else if constexpr (MODE == 2) {
            float a0 = 0.f, a1 = 0.f;
            if (n <= m)     { float s = v0 * (1.f/256.f) + g_biastab[m - n];     s = fmaxf(s, 0.f); a0 = s * s; }
            if (n + 1 <= m) { float s = v1 * (1.f/256.f) + g_biastab[m - n - 1]; s = fmaxf(s, 0.f); a1 = s * s; }
            *reinterpret_cast<float2*>(g_attn + (size_t)bg * GQ * GQ + (size_t)m * GQ + n)
                = make_float2(a0, a1);
        } else if constexpr (MODE == 3) {
            *reinterpret_cast<float2*>(g_linkv + (size_t)bg * QKD * HIDX + (size_t)m * HIDX + n)
                = make_float2(v0 * (1.f/256.f), v1 * (1.f/256.f));
        } else if constexpr (MODE == 4) {
            size_t row = (size_t)(bg * GQ + m);
            float2 gt = *reinterpret_cast<const float2*>(g_gate + row * HIDX + n);
            *reinterpret_cast<float2*>(g_act + row * HIDX + n)
                = make_float2(v0 * gt.x, v1 * gt.y);
        } else {
            size_t off = (size_t)m * DIMX + n;
            float2 xr = *reinterpret_cast<const float2*>(xres + off);
            *reinterpret_cast<float2*>(out + off)
                = make_float2(v0 + bias[n] + xr.x, v1 + bias[n + 1] + xr.y);
        }
    }
}

// ---------------- host launcher ----------------
extern "C" void kernel_launch(void* const* d_in, const int* in_sizes, int n_in,
                              void* d_out, int out_size) {
    const float* x         = (const float*)d_in[0];
    const float* ln_w      = (const float*)d_in[1];
    const float* ln_b      = (const float*)d_in[2];
    const float* Wh        = (const float*)d_in[3];
    const float* bh        = (const float*)d_in[4];
    const float* Wqk       = (const float*)d_in[5];
    const float* bqk       = (const float*)d_in[6];
    const float* qk_w      = (const float*)d_in[7];
    const float* qk_b      = (const float*)d_in[8];
    const float* rel_table = (const float*)d_in[9];
    const float* Wout      = (const float*)d_in[10];
    const float* bout      = (const float*)d_in[11];
    float* out = (float*)d_out;

    cudaFuncSetAttribute(gemm_kernel<0>, cudaFuncAttributeMaxDynamicSharedMemorySize, SMEM_BYTES);
    cudaFuncSetAttribute(gemm_kernel<1>, cudaFuncAttributeMaxDynamicSharedMemorySize, SMEM_BYTES);
    cudaFuncSetAttribute(gemm_kernel<2>, cudaFuncAttributeMaxDynamicSharedMemorySize, SMEM_BYTES);
    cudaFuncSetAttribute(gemm_kernel<3>, cudaFuncAttributeMaxDynamicSharedMemorySize, SMEM_BYTES);
    cudaFuncSetAttribute(gemm_kernel<4>, cudaFuncAttributeMaxDynamicSharedMemorySize, SMEM_BYTES);
    cudaFuncSetAttribute(gemm_kernel<5>, cudaFuncAttributeMaxDynamicSharedMemorySize, SMEM_BYTES);

    prep_kernel<<<1, 256>>>(rel_table);
    ln_kernel<<<NTOK, 256>>>(x, ln_w, ln_b);
    gemm_kernel<0><<<dim3(128, 32, 1), 256, SMEM_BYTES>>>(Wh, bh, nullptr, nullptr);
    gemm_kernel<1><<<dim3(128, 1, 1), 256, SMEM_BYTES>>>(Wqk, bqk, nullptr, nullptr);
    qkhead_kernel<<<NTOK, 128>>>(qk_w, qk_b);
    gemm_kernel<2><<<dim3(2, 2, 64), 256, SMEM_BYTES>>>(nullptr, nullptr, nullptr, nullptr);
    gemm_kernel<3><<<dim3(1, 16, 64), 256, SMEM_BYTES>>>(nullptr, nullptr, nullptr, nullptr);
    cumsum_kernel<<<4096, 256>>>();
    gemm_kernel<4><<<dim3(2, 16, 64), 256, SMEM_BYTES>>>(nullptr, nullptr, nullptr, nullptr);
    gemm_kernel<5><<<dim3(128, 8, 1), 256, SMEM_BYTES>>>(Wout, bout, x, out);
}

// round 4
// speedup vs baseline: 1.0337x; 1.0337x over previous
#include <cuda_runtime.h>
#include <cuda_bf16.h>
#include <cstdint>
#include <math.h>

#define DIMX  1024
#define GQ    256
#define QKD   128
#define HIDX  2048
#define NTOK  16384
#define NBG   64

// ---------------- scratch (device globals; no allocation) ----------------
__device__ float g_normed[(size_t)NTOK * DIMX];
__device__ float g_v    [(size_t)NTOK * HIDX];
__device__ float g_gate [(size_t)NTOK * HIDX];
__device__ float g_qksilu[(size_t)NTOK * QKD];
__device__ float g_qq   [(size_t)NTOK * QKD];
__device__ float g_lq   [(size_t)NTOK * QKD];
__device__ float g_qkT  [(size_t)NBG * QKD * GQ];
__device__ float g_lkT  [(size_t)NBG * QKD * GQ];
__device__ float g_attn [(size_t)NBG * GQ * GQ];
__device__ float g_linkv[(size_t)NBG * QKD * HIDX];
__device__ float g_linkvc[(size_t)NBG * QKD * HIDX];
__device__ float g_act  [(size_t)NTOK * HIDX];
__device__ float g_biastab[GQ];
// tf32-pre-rounded weights
__device__ float g_Whr  [(size_t)DIMX * 2 * HIDX];
__device__ float g_Wqkr [(size_t)DIMX * QKD];
__device__ float g_Woutr[(size_t)HIDX * DIMX];

// ---------------- small helpers ----------------
__device__ __forceinline__ float silu_f(float x) { return x / (1.0f + expf(-x)); }

__device__ __forceinline__ float tfr(float f) {        // round fp32 -> tf32 (bits in fp32)
    uint32_t r;
    asm("cvt.rna.tf32.f32 %0, %1;" : "=r"(r) : "f"(f));
    return __uint_as_float(r);
}
__device__ __forceinline__ void mma_tf32(float (&d)[4], const uint32_t (&a)[4],
                                         uint32_t b0, uint32_t b1) {
    asm volatile(
        "mma.sync.aligned.m16n8k8.row.col.f32.tf32.tf32.f32 "
        "{%0,%1,%2,%3}, {%4,%5,%6,%7}, {%8,%9}, {%0,%1,%2,%3};\n"
        : "+f"(d[0]), "+f"(d[1]), "+f"(d[2]), "+f"(d[3])
        : "r"(a[0]), "r"(a[1]), "r"(a[2]), "r"(a[3]), "r"(b0), "r"(b1));
}

// ---------------- prep: T5 bias table ----------------
__global__ void prep_kernel(const float* __restrict__ rel_table) {
    int n = threadIdx.x;   // causal distance 0..255
    int bucket;
    if (n < 16) bucket = n;
    else {
        int v = 16 + (int)(logf((float)n / 16.0f) / logf(8.0f) * 16.0f);
        bucket = v < 31 ? v : 31;
    }
    g_biastab[n] = rel_table[bucket] * sqrtf(128.0f);
}

// ---------------- prep: round weights to tf32 ----------------
__global__ void prep_w_kernel(const float* __restrict__ Wh, const float* __restrict__ Wqk,
                              const float* __restrict__ Wout) {
    int i = blockIdx.x * 256 + threadIdx.x;      // 1,048,576 threads
    const int nh = DIMX * 2 * HIDX / 4;          // 1,048,576 float4
    const int nq = DIMX * QKD / 4;               // 32,768
    const int no = HIDX * DIMX / 4;              // 524,288
    if (i < nh) {
        float4 f = reinterpret_cast<const float4*>(Wh)[i];
        f.x = tfr(f.x); f.y = tfr(f.y); f.z = tfr(f.z); f.w = tfr(f.w);
        reinterpret_cast<float4*>(g_Whr)[i] = f;
    }
    if (i < nq) {
        float4 f = reinterpret_cast<const float4*>(Wqk)[i];
        f.x = tfr(f.x); f.y = tfr(f.y); f.z = tfr(f.z); f.w = tfr(f.w);
        reinterpret_cast<float4*>(g_Wqkr)[i] = f;
    }
    if (i < no) {
        float4 f = reinterpret_cast<const float4*>(Wout)[i];
        f.x = tfr(f.x); f.y = tfr(f.y); f.z = tfr(f.z); f.w = tfr(f.w);
        reinterpret_cast<float4*>(g_Woutr)[i] = f;
    }
}

// ---------------- LayerNorm -> fp32 (tf32-rounded) ----------------
__global__ void ln_kernel(const float* __restrict__ x, const float* __restrict__ w,
                          const float* __restrict__ b) {
    int row = blockIdx.x, t = threadIdx.x;   // 256 threads, 4 floats each
    float4 f = reinterpret_cast<const float4*>(x + (size_t)row * DIMX)[t];
    float s  = f.x + f.y + f.z + f.w;
    float s2 = f.x*f.x + f.y*f.y + f.z*f.z + f.w*f.w;
    #pragma unroll
    for (int o = 16; o; o >>= 1) {
        s  += __shfl_xor_sync(0xffffffffu, s,  o);
        s2 += __shfl_xor_sync(0xffffffffu, s2, o);
    }
    __shared__ float ss[8], ss2[8], smu, sinv;
    if ((t & 31) == 0) { ss[t >> 5] = s; ss2[t >> 5] = s2; }
    __syncthreads();
    if (t == 0) {
        float S = 0.f, S2 = 0.f;
        #pragma unroll
        for (int k = 0; k < 8; k++) { S += ss[k]; S2 += ss2[k]; }
        float mu  = S * (1.0f / 1024.0f);
        float var = S2 * (1.0f / 1024.0f) - mu * mu;
        smu = mu; sinv = rsqrtf(var + 1e-5f);
    }
    __syncthreads();
    float mu = smu, inv = sinv;
    float4 wv = reinterpret_cast<const float4*>(w)[t];
    float4 bv = reinterpret_cast<const float4*>(b)[t];
    float4 o;
    o.x = tfr((f.x - mu)*inv*wv.x + bv.x);
    o.y = tfr((f.y - mu)*inv*wv.y + bv.y);
    o.z = tfr((f.z - mu)*inv*wv.z + bv.z);
    o.w = tfr((f.w - mu)*inv*wv.w + bv.w);
    reinterpret_cast<float4*>(g_normed + (size_t)row * DIMX)[t] = o;
}

// ---------------- head expand: qk_silu -> 4 heads (k heads transposed per group) ---
__global__ void qkhead_kernel(const float* __restrict__ qk_w, const float* __restrict__ qk_b) {
    int t = blockIdx.x;        // token
    int d = threadIdx.x;       // 0..127
    float v = g_qksilu[(size_t)t * QKD + d];
    int bg = t >> 8, nl = t & 255;
    g_qq[(size_t)t * QKD + d] = tfr(v * qk_w[d]         + qk_b[d]);
    g_lq[(size_t)t * QKD + d] = tfr(v * qk_w[QKD + d]   + qk_b[QKD + d]);
    g_qkT[(size_t)bg * QKD * GQ + (size_t)d * GQ + nl] = tfr(v * qk_w[2*QKD + d] + qk_b[2*QKD + d]);
    g_lkT[(size_t)bg * QKD * GQ + (size_t)d * GQ + nl] = tfr(v * qk_w[3*QKD + d] + qk_b[3*QKD + d]);
}

// ---------------- exclusive cumsum over groups (fp32, tf32-rounded out) ----------
__global__ void cumsum_kernel() {
    int i  = blockIdx.x * 256 + threadIdx.x;     // < 4*2^18
    int b  = i >> 18;
    int de = i & ((1 << 18) - 1);                // 128*2048 = 2^18
    float a = 0.f;
    #pragma unroll
    for (int g = 0; g < 16; g++) {
        size_t off = ((size_t)(b * 16 + g) << 18) + de;
        g_linkvc[off] = tfr(a);
        a += g_linkv[off];
    }
}

// ---------------- generic tf32 MMA GEMM, 128x128x32 tile, 6 modes ----------------
// MODE 0: normed@Wh  +bh, silu, split v/gate      M=16384 N=4096 K=1024
// MODE 1: normed@Wqk +bqk, silu -> qksilu         M=16384 N=128  K=1024
// MODE 2: sim = qq@qkT /256 +bias, relu^2, mask   M=256b  N=256  K=128
// MODE 3: linkv = lkT@v /256                      M=128b  N=2048 K=256
// MODE 4: [attn|lq]@[v;linkvc], * gate -> act     M=256b  N=2048 K=384
// MODE 5: act@Wout +bout +x -> out                M=16384 N=1024 K=2048
constexpr int KDIM[6] = {1024, 1024, 128, 256, 384, 2048};

#define ASTRIDE 36
#define BSTRIDE 132
#define A_BUF   (128 * ASTRIDE)
#define B_BUF   (32 * BSTRIDE)
#define SMEM_BYTES ((2 * A_BUF + 2 * B_BUF) * 4)

template<int MODE>
__device__ __forceinline__ const float* a_ptr(int bg, int m, int k) {
    if constexpr (MODE == 0 || MODE == 1) return g_normed + (size_t)m * DIMX + k;
    else if constexpr (MODE == 2) return g_qq + ((size_t)bg * GQ + m) * QKD + k;
    else if constexpr (MODE == 3) return g_lkT + (size_t)bg * QKD * GQ + (size_t)m * GQ + k;
    else if constexpr (MODE == 4) {
        if (k < GQ) return g_attn + (size_t)bg * GQ * GQ + (size_t)m * GQ + k;
        else        return g_lq + ((size_t)bg * GQ + m) * QKD + (k - GQ);
    }
    else return g_act + (size_t)m * HIDX + k;
}
template<int MODE>
__device__ __forceinline__ const float* b_ptr(int bg, int k, int n) {
    if constexpr (MODE == 0) return g_Whr + (size_t)k * (2 * HIDX) + n;
    else if constexpr (MODE == 1) return g_Wqkr + (size_t)k * QKD + n;
    else if constexpr (MODE == 2) return g_qkT + (size_t)bg * QKD * GQ + (size_t)k * GQ + n;
    else if constexpr (MODE == 3) return g_v + ((size_t)bg * GQ + k) * HIDX + n;
    else if constexpr (MODE == 4) {
        if (k < GQ) return g_v + ((size_t)bg * GQ + k) * HIDX + n;
        else        return g_linkvc + (size_t)bg * QKD * HIDX + (size_t)(k - GQ) * HIDX + n;
    }
    else return g_Woutr + (size_t)k * DIMX + n;
}

template<int MODE>
__global__ void __launch_bounds__(256) gemm_kernel(const float* __restrict__ bias,
                                                   const float* __restrict__ xres,
                                                   float* __restrict__ out) {
    constexpr int K  = KDIM[MODE];
    constexpr int KT = K / 32;
    extern __shared__ float smem[];
    float* As = smem;                 // [2][128][ASTRIDE]
    float* Bs = smem + 2 * A_BUF;     // [2][32][BSTRIDE]

    const int tid = threadIdx.x;
    int bx = blockIdx.x, by = blockIdx.y;
    if constexpr (MODE == 2) {        // lower-triangular blocks only: (0,0),(1,0),(1,1)
        int t = blockIdx.x;
        bx = (t + 1) >> 1;
        by = t >> 1;
    }
    const int m0 = bx * 128;
    const int n0 = by * 128;
    const int bg = blockIdx.z;
    const int warp = tid >> 5, lane = tid & 31;
    const int wm = warp & 3, wn = warp >> 2;           // 4x2 warps -> 32x64 each
    const int gid = lane >> 2, tig = lane & 3;         // fragment addressing
    const int lm = lane >> 2, ln = (lane & 3) << 1;    // C-fragment addressing

    uint32_t sA = (uint32_t)__cvta_generic_to_shared(As);
    uint32_t sB = (uint32_t)__cvta_generic_to_shared(Bs);

    float acc[2][8][4];
    #pragma unroll
    for (int a = 0; a < 2; a++)
        #pragma unroll
        for (int b = 0; b < 8; b++)
            #pragma unroll
            for (int c = 0; c < 4; c++) acc[a][b][c] = 0.f;

    auto load_tile = [&](int kt, int buf) {
        int k0 = kt * 32;
        #pragma unroll
        for (int it = 0; it < 4; it++) {                    // A: 128x32 fp32, 16B chunks
            int idx = tid + it * 256;
            int r = idx >> 3, kc = (idx & 7) << 2;
            const float* gp = a_ptr<MODE>(bg, m0 + r, k0 + kc);
            uint32_t sa = sA + ((buf * 128 + r) * ASTRIDE + kc) * 4;
            asm volatile("cp.async.cg.shared.global [%0], [%1], 16;\n" :: "r"(sa), "l"(gp));
        }
        #pragma unroll
        for (int it = 0; it < 4; it++) {                    // B: 32x128 fp32
            int idx = tid + it * 256;
            int r = idx >> 5, nc = (idx & 31) << 2;
            const float* gp = b_ptr<MODE>(bg, k0 + r, n0 + nc);
            uint32_t sb = sB + ((buf * 32 + r) * BSTRIDE + nc) * 4;
            asm volatile("cp.async.cg.shared.global [%0], [%1], 16;\n" :: "r"(sb), "l"(gp));
        }
        asm volatile("cp.async.commit_group;\n");
    };

    load_tile(0, 0);
    for (int kt = 0; kt < KT; kt++) {
        int cur = kt & 1;
        if (kt + 1 < KT) {
            load_tile(kt + 1, cur ^ 1);
            asm volatile("cp.async.wait_group 1;\n");
        } else {
            asm volatile("cp.async.wait_group 0;\n");
        }
        __syncthreads();
        #pragma unroll
        for (int ks = 0; ks < 32; ks += 8) {
            uint32_t af[2][4], bfr[8][2];
            #pragma unroll
            for (int mf = 0; mf < 2; mf++) {
                const uint32_t* ab = reinterpret_cast<const uint32_t*>(
                    As + (cur * 128 + wm * 32 + mf * 16 + gid) * ASTRIDE + ks + tig);
                af[mf][0] = ab[0];
                af[mf][1] = ab[8 * ASTRIDE];
                af[mf][2] = ab[4];
                af[mf][3] = ab[8 * ASTRIDE + 4];
            }
            #pragma unroll
            for (int nt = 0; nt < 8; nt++) {
                const uint32_t* bb = reinterpret_cast<const uint32_t*>(
                    Bs + (cur * 32 + ks + tig) * BSTRIDE + wn * 64 + nt * 8 + gid);
                bfr[nt][0] = bb[0];
                bfr[nt][1] = bb[4 * BSTRIDE];
            }
            #pragma unroll
            for (int mf = 0; mf < 2; mf++)
                #pragma unroll
                for (int nf = 0; nf < 8; nf++)
                    mma_tf32(acc[mf][nf], af[mf], bfr[nf][0], bfr[nf][1]);
        }
        __syncthreads();
    }

    // -------- epilogue --------
    #pragma unroll
    for (int mf = 0; mf < 2; mf++)
    #pragma unroll
    for (int nf = 0; nf < 8; nf++)
    #pragma unroll
    for (int h = 0; h < 2; h++) {
        int m = m0 + wm * 32 + mf * 16 + lm + h * 8;
        int n = n0 + wn * 64 + nf * 8 + ln;
        float v0 = acc[mf][nf][h * 2 + 0];
        float v1 = acc[mf][nf][h * 2 + 1];
        if constexpr (MODE == 0) {
            float h0 = silu_f(v0 + bias[n]);
            float h1 = silu_f(v1 + bias[n + 1]);
            if (n < HIDX)
                *reinterpret_cast<float2*>(g_v + (size_t)m * HIDX + n)
                    = make_float2(tfr(h0), tfr(h1));
            else
                *reinterpret_cast<float2*>(g_gate + (size_t)m * HIDX + (n - HIDX)) = make_float2(h0, h1);
        } else if constexpr (MODE == 1) {
            float h0 = silu_f(v0 + bias[n]);
            float h1 = silu_f(v1 + bias[n + 1]);
            *reinterpret_cast<float2*>(g_qksilu + (size_t)m * QKD + n) = make_float2(h0, h1);
        } else if constexpr (MODE == 2) {
            float a0 = 0.f, a1 = 0.f;
            if (n <= m)     { float s = v0 * (1.f/256.f) + g_biastab[m - n];     s = fmaxf(s, 0.f); a0 = s * s; }
            if (n + 1 <= m) { float s = v1 * (1.f/256.f) + g_biastab[m - n - 1]; s = fmaxf(s, 0.f); a1 = s * s; }
            *reinterpret_cast<float2*>(g_attn + (size_t)bg * GQ * GQ + (size_t)m * GQ + n)
                = make_float2(tfr(a0), tfr(a1));
        } else if constexpr (MODE == 3) {
            *reinterpret_cast<float2*>(g_linkv + (size_t)bg * QKD * HIDX + (size_t)m * HIDX + n)
                = make_float2(v0 * (1.f/256.f), v1 * (1.f/256.f));
        } else if constexpr (MODE == 4) {
            size_t row = (size_t)(bg * GQ + m);
            float2 gt = *reinterpret_cast<const float2*>(g_gate + row * HIDX + n);
            *reinterpret_cast<float2*>(g_act + row * HIDX + n)
                = make_float2(tfr(v0 * gt.x), tfr(v1 * gt.y));
        } else {
            size_t off = (size_t)m * DIMX + n;
            float2 xr = *reinterpret_cast<const float2*>(xres + off);
            *reinterpret_cast<float2*>(out + off)
                = make_float2(v0 + bias[n] + xr.x, v1 + bias[n + 1] + xr.y);
        }
    }
}

// ---------------- host launcher ----------------
extern "C" void kernel_launch(void* const* d_in, const int* in_sizes, int n_in,
                              void* d_out, int out_size) {
    const float* x         = (const float*)d_in[0];
    const float* ln_w      = (const float*)d_in[1];
    const float* ln_b      = (const float*)d_in[2];
    const float* Wh        = (const float*)d_in[3];
    const float* bh        = (const float*)d_in[4];
    const float* Wqk       = (const float*)d_in[5];
    const float* bqk       = (const float*)d_in[6];
    const float* qk_w      = (const float*)d_in[7];
    const float* qk_b      = (const float*)d_in[8];
    const float* rel_table = (const float*)d_in[9];
    const float* Wout      = (const float*)d_in[10];
    const float* bout      = (const float*)d_in[11];
    float* out = (float*)d_out;

    cudaFuncSetAttribute(gemm_kernel<0>, cudaFuncAttributeMaxDynamicSharedMemorySize, SMEM_BYTES);
    cudaFuncSetAttribute(gemm_kernel<1>, cudaFuncAttributeMaxDynamicSharedMemorySize, SMEM_BYTES);
    cudaFuncSetAttribute(gemm_kernel<2>, cudaFuncAttributeMaxDynamicSharedMemorySize, SMEM_BYTES);
    cudaFuncSetAttribute(gemm_kernel<3>, cudaFuncAttributeMaxDynamicSharedMemorySize, SMEM_BYTES);
    cudaFuncSetAttribute(gemm_kernel<4>, cudaFuncAttributeMaxDynamicSharedMemorySize, SMEM_BYTES);
    cudaFuncSetAttribute(gemm_kernel<5>, cudaFuncAttributeMaxDynamicSharedMemorySize, SMEM_BYTES);

    prep_kernel<<<1, 256>>>(rel_table);
    prep_w_kernel<<<4096, 256>>>(Wh, Wqk, Wout);
    ln_kernel<<<NTOK, 256>>>(x, ln_w, ln_b);
    gemm_kernel<0><<<dim3(128, 32, 1), 256, SMEM_BYTES>>>(bh, nullptr, nullptr);
    gemm_kernel<1><<<dim3(128, 1, 1), 256, SMEM_BYTES>>>(bqk, nullptr, nullptr);
    qkhead_kernel<<<NTOK, 128>>>(qk_w, qk_b);
    gemm_kernel<2><<<dim3(3, 1, 64), 256, SMEM_BYTES>>>(nullptr, nullptr, nullptr);
    gemm_kernel<3><<<dim3(1, 16, 64), 256, SMEM_BYTES>>>(nullptr, nullptr, nullptr);
    cumsum_kernel<<<4096, 256>>>();
    gemm_kernel<4><<<dim3(2, 16, 64), 256, SMEM_BYTES>>>(nullptr, nullptr, nullptr);
    gemm_kernel<5><<<dim3(128, 8, 1), 256, SMEM_BYTES>>>(bout, x, out);
}

// round 9
// speedup vs baseline: 1.0956x; 1.0600x over previous
#include <cuda_runtime.h>
#include <cuda_bf16.h>
#include <cstdint>
#include <math.h>

#define DIMX  1024
#define GQ    256
#define QKD   128
#define HIDX  2048
#define NTOK  16384
#define NBG   64

// ---------------- scratch (device globals; no allocation) ----------------
__device__ float g_normed[(size_t)NTOK * DIMX];
__device__ float g_v    [(size_t)NTOK * HIDX];
__device__ float g_gate [(size_t)NTOK * HIDX];
__device__ float g_qksilu[(size_t)NTOK * QKD];
__device__ float g_qq   [(size_t)NTOK * QKD];
__device__ float g_lq   [(size_t)NTOK * QKD];
__device__ float g_qkT  [(size_t)NBG * QKD * GQ];
__device__ float g_lkT  [(size_t)NBG * QKD * GQ];
__device__ float g_attn [(size_t)NBG * GQ * GQ];
__device__ float g_linkv[(size_t)NBG * QKD * HIDX];
__device__ float g_linkvc[(size_t)NBG * QKD * HIDX];
__device__ float g_act  [(size_t)NTOK * HIDX];
__device__ float g_biastab[GQ];
// tf32-pre-rounded, K-major (transposed) weights
__device__ float g_WhT  [(size_t)(2 * HIDX) * DIMX];   // [4096][1024]
__device__ float g_WqkT [(size_t)QKD * DIMX];          // [128][1024]
__device__ float g_WoutT[(size_t)DIMX * HIDX];         // [1024][2048]

// ---------------- small helpers ----------------
__device__ __forceinline__ float silu_f(float x) { return x / (1.0f + expf(-x)); }

__device__ __forceinline__ float tfr(float f) {        // round fp32 -> tf32 (bits in fp32)
    uint32_t r;
    asm("cvt.rna.tf32.f32 %0, %1;" : "=r"(r) : "f"(f));
    return __uint_as_float(r);
}
__device__ __forceinline__ void mma_tf32(float (&d)[4], const uint32_t (&a)[4],
                                         uint32_t b0, uint32_t b1) {
    asm volatile(
        "mma.sync.aligned.m16n8k8.row.col.f32.tf32.tf32.f32 "
        "{%0,%1,%2,%3}, {%4,%5,%6,%7}, {%8,%9}, {%0,%1,%2,%3};\n"
        : "+f"(d[0]), "+f"(d[1]), "+f"(d[2]), "+f"(d[3])
        : "r"(a[0]), "r"(a[1]), "r"(a[2]), "r"(a[3]), "r"(b0), "r"(b1));
}

// ---------------- prep: T5 bias table ----------------
__global__ void prep_kernel(const float* __restrict__ rel_table) {
    int n = threadIdx.x;   // causal distance 0..255
    int bucket;
    if (n < 16) bucket = n;
    else {
        int v = 16 + (int)(logf((float)n / 16.0f) / logf(8.0f) * 16.0f);
        bucket = v < 31 ? v : 31;
    }
    g_biastab[n] = rel_table[bucket] * sqrtf(128.0f);
}

// ---------------- transpose + tf32 round: src[R][C] -> dst[C][R] ----------------
__global__ void transpose_kernel(const float* __restrict__ src, float* __restrict__ dst,
                                 int R, int C) {
    __shared__ float t[32][33];
    int c0 = blockIdx.x * 32, r0 = blockIdx.y * 32;
    int tx = threadIdx.x, ty = threadIdx.y;   // 32 x 8
    #pragma unroll
    for (int j = 0; j < 32; j += 8)
        t[ty + j][tx] = tfr(src[(size_t)(r0 + ty + j) * C + c0 + tx]);
    __syncthreads();
    #pragma unroll
    for (int j = 0; j < 32; j += 8)
        dst[(size_t)(c0 + ty + j) * R + r0 + tx] = t[tx][ty + j];
}

// ---------------- LayerNorm -> fp32 (tf32-rounded) ----------------
__global__ void ln_kernel(const float* __restrict__ x, const float* __restrict__ w,
                          const float* __restrict__ b) {
    int row = blockIdx.x, t = threadIdx.x;   // 256 threads, 4 floats each
    float4 f = reinterpret_cast<const float4*>(x + (size_t)row * DIMX)[t];
    float s  = f.x + f.y + f.z + f.w;
    float s2 = f.x*f.x + f.y*f.y + f.z*f.z + f.w*f.w;
    #pragma unroll
    for (int o = 16; o; o >>= 1) {
        s  += __shfl_xor_sync(0xffffffffu, s,  o);
        s2 += __shfl_xor_sync(0xffffffffu, s2, o);
    }
    __shared__ float ss[8], ss2[8], smu, sinv;
    if ((t & 31) == 0) { ss[t >> 5] = s; ss2[t >> 5] = s2; }
    __syncthreads();
    if (t == 0) {
        float S = 0.f, S2 = 0.f;
        #pragma unroll
        for (int k = 0; k < 8; k++) { S += ss[k]; S2 += ss2[k]; }
        float mu  = S * (1.0f / 1024.0f);
        float var = S2 * (1.0f / 1024.0f) - mu * mu;
        smu = mu; sinv = rsqrtf(var + 1e-5f);
    }
    __syncthreads();
    float mu = smu, inv = sinv;
    float4 wv = reinterpret_cast<const float4*>(w)[t];
    float4 bv = reinterpret_cast<const float4*>(b)[t];
    float4 o;
    o.x = tfr((f.x - mu)*inv*wv.x + bv.x);
    o.y = tfr((f.y - mu)*inv*wv.y + bv.y);
    o.z = tfr((f.z - mu)*inv*wv.z + bv.z);
    o.w = tfr((f.w - mu)*inv*wv.w + bv.w);
    reinterpret_cast<float4*>(g_normed + (size_t)row * DIMX)[t] = o;
}

// ---------------- head expand ----------------
__global__ void qkhead_kernel(const float* __restrict__ qk_w, const float* __restrict__ qk_b) {
    int t = blockIdx.x;        // token
    int d = threadIdx.x;       // 0..127
    float v = g_qksilu[(size_t)t * QKD + d];
    int bg = t >> 8, nl = t & 255;
    g_qq[(size_t)t * QKD + d] = tfr(v * qk_w[d]         + qk_b[d]);
    g_lq[(size_t)t * QKD + d] = tfr(v * qk_w[QKD + d]   + qk_b[QKD + d]);
    g_qkT[(size_t)bg * QKD * GQ + (size_t)d * GQ + nl] = tfr(v * qk_w[2*QKD + d] + qk_b[2*QKD + d]);
    g_lkT[(size_t)bg * QKD * GQ + (size_t)d * GQ + nl] = tfr(v * qk_w[3*QKD + d] + qk_b[3*QKD + d]);
}

// ---------------- exclusive cumsum over groups ----------------
__global__ void cumsum_kernel() {
    int i  = blockIdx.x * 256 + threadIdx.x;
    int b  = i >> 18;
    int de = i & ((1 << 18) - 1);
    float a = 0.f;
    #pragma unroll
    for (int g = 0; g < 16; g++) {
        size_t off = ((size_t)(b * 16 + g) << 18) + de;
        g_linkvc[off] = tfr(a);
        a += g_linkv[off];
    }
}

// ================= tf32 MMA GEMM, 128x128x32 tile, 6 modes ==================
// MODE 0: normed@WhT'  +bh, silu, split v/gate    M=16384 N=4096 K=1024  (B K-major)
// MODE 1: normed@WqkT' +bqk, silu -> qksilu       M=16384 N=128  K=1024  (B K-major)
// MODE 2: sim = qq@qkT /256 +bias, relu^2, mask   M=256b  N=256  K=128
// MODE 3: linkv = lkT@v /256                      M=128b  N=2048 K=256
// MODE 4: [attn|lq]@[v;linkvc], * gate -> act     M=256b  N=2048 K=384
// MODE 5: act@WoutT'  +bout +x -> out             M=16384 N=1024 K=2048  (B K-major)
constexpr int KDIM[6] = {1024, 1024, 128, 256, 384, 2048};
constexpr bool BKMAJ[6] = {true, true, false, false, false, true};

#define ASTRIDE 40
#define BSTRIDE 132
#define A_BUF   (128 * ASTRIDE)
#define BBUF(MODE)  (BKMAJ[MODE] ? 128 * ASTRIDE : 32 * BSTRIDE)
#define SMEMB(MODE) ((2 * A_BUF + 2 * BBUF(MODE)) * 4)

template<int MODE>
__device__ __forceinline__ const float* a_ptr(int bg, int m, int k) {
    if constexpr (MODE == 0 || MODE == 1) return g_normed + (size_t)m * DIMX + k;
    else if constexpr (MODE == 2) return g_qq + ((size_t)bg * GQ + m) * QKD + k;
    else if constexpr (MODE == 3) return g_lkT + (size_t)bg * QKD * GQ + (size_t)m * GQ + k;
    else if constexpr (MODE == 4) {
        if (k < GQ) return g_attn + (size_t)bg * GQ * GQ + (size_t)m * GQ + k;
        else        return g_lq + ((size_t)bg * GQ + m) * QKD + (k - GQ);
    }
    else return g_act + (size_t)m * HIDX + k;
}
// K-major B (weights): (n, k)
template<int MODE>
__device__ __forceinline__ const float* bkm_ptr(int n, int k) {
    if constexpr (MODE == 0) return g_WhT + (size_t)n * DIMX + k;
    else if constexpr (MODE == 1) return g_WqkT + (size_t)n * DIMX + k;
    else return g_WoutT + (size_t)n * HIDX + k;
}
// N-major B (activations): (k, n)
template<int MODE>
__device__ __forceinline__ const float* bnm_ptr(int bg, int k, int n) {
    if constexpr (MODE == 2) return g_qkT + (size_t)bg * QKD * GQ + (size_t)k * GQ + n;
    else if constexpr (MODE == 3) return g_v + ((size_t)bg * GQ + k) * HIDX + n;
    else {
        if (k < GQ) return g_v + ((size_t)bg * GQ + k) * HIDX + n;
        else        return g_linkvc + (size_t)bg * QKD * HIDX + (size_t)(k - GQ) * HIDX + n;
    }
}

template<int MODE>
__global__ void __launch_bounds__(256) gemm_kernel(const float* __restrict__ bias,
                                                   const float* __restrict__ xres,
                                                   float* __restrict__ out) {
    constexpr int K  = KDIM[MODE];
    constexpr int KT = K / 32;
    constexpr bool BK = BKMAJ[MODE];
    constexpr int B_BUF = BK ? 128 * ASTRIDE : 32 * BSTRIDE;
    extern __shared__ float smem[];
    float* As = smem;                 // [2][128][ASTRIDE]
    float* Bs = smem + 2 * A_BUF;     // BK: [2][128][ASTRIDE]  else [2][32][BSTRIDE]

    const int tid = threadIdx.x;
    int bx = blockIdx.x, by = blockIdx.y;
    if constexpr (MODE == 2) {        // lower-triangular blocks only: (0,0),(1,0),(1,1)
        int t = blockIdx.x;
        bx = (t + 1) >> 1;
        by = t >> 1;
    }
    const int m0 = bx * 128;
    const int n0 = by * 128;
    const int bg = blockIdx.z;
    const int warp = tid >> 5, lane = tid & 31;
    const int wm = warp & 3, wn = warp >> 2;           // 4x2 warps -> 32x64 each
    const int gid = lane >> 2, tig = lane & 3;         // fragment addressing
    const int lm = lane >> 2, ln = (lane & 3) << 1;    // C-fragment addressing

    uint32_t sA = (uint32_t)__cvta_generic_to_shared(As);
    uint32_t sB = (uint32_t)__cvta_generic_to_shared(Bs);

    float acc[2][8][4];
    #pragma unroll
    for (int a = 0; a < 2; a++)
        #pragma unroll
        for (int b = 0; b < 8; b++)
            #pragma unroll
            for (int c = 0; c < 4; c++) acc[a][b][c] = 0.f;

    auto load_tile = [&](int kt, int buf) {
        int k0 = kt * 32;
        #pragma unroll
        for (int it = 0; it < 4; it++) {                    // A: 128x32 fp32, 16B chunks
            int idx = tid + it * 256;
            int r = idx >> 3, kc = (idx & 7) << 2;
            const float* gp = a_ptr<MODE>(bg, m0 + r, k0 + kc);
            uint32_t sa = sA + ((buf * 128 + r) * ASTRIDE + kc) * 4;
            asm volatile("cp.async.cg.shared.global [%0], [%1], 16;\n" :: "r"(sa), "l"(gp));
        }
        if constexpr (BK) {
            #pragma unroll
            for (int it = 0; it < 4; it++) {                // B: 128n x 32k
                int idx = tid + it * 256;
                int r = idx >> 3, kc = (idx & 7) << 2;
                const float* gp = bkm_ptr<MODE>(n0 + r, k0 + kc);
                uint32_t sb = sB + ((buf * 128 + r) * ASTRIDE + kc) * 4;
                asm volatile("cp.async.cg.shared.global [%0], [%1], 16;\n" :: "r"(sb), "l"(gp));
            }
        } else {
            #pragma unroll
            for (int it = 0; it < 4; it++) {                // B: 32k x 128n
                int idx = tid + it * 256;
                int r = idx >> 5, nc = (idx & 31) << 2;
                const float* gp = bnm_ptr<MODE>(bg, k0 + r, n0 + nc);
                uint32_t sb = sB + ((buf * 32 + r) * BSTRIDE + nc) * 4;
                asm volatile("cp.async.cg.shared.global [%0], [%1], 16;\n" :: "r"(sb), "l"(gp));
            }
        }
        asm volatile("cp.async.commit_group;\n");
    };

    load_tile(0, 0);
    for (int kt = 0; kt < KT; kt++) {
        int cur = kt & 1;
        if (kt + 1 < KT) {
            load_tile(kt + 1, cur ^ 1);
            asm volatile("cp.async.wait_group 1;\n");
        } else {
            asm volatile("cp.async.wait_group 0;\n");
        }
        __syncthreads();
        // k-permutation: logical frag slots {tig, tig+4} read physical cols {2tig, 2tig+1}
        #pragma unroll
        for (int ks = 0; ks < 32; ks += 8) {
            uint32_t af[2][4], bfr[8][2];
            #pragma unroll
            for (int mf = 0; mf < 2; mf++) {
                const float* abase = As + (cur * 128 + wm * 32 + mf * 16 + gid) * ASTRIDE + ks + 2 * tig;
                uint2 l0 = *reinterpret_cast<const uint2*>(abase);
                uint2 l1 = *reinterpret_cast<const uint2*>(abase + 8 * ASTRIDE);
                af[mf][0] = l0.x; af[mf][1] = l1.x; af[mf][2] = l0.y; af[mf][3] = l1.y;
            }
            #pragma unroll
            for (int nt = 0; nt < 8; nt++) {
                int col = wn * 64 + nt * 8 + gid;
                if constexpr (BK) {
                    uint2 b2 = *reinterpret_cast<const uint2*>(
                        Bs + (cur * 128 + col) * ASTRIDE + ks + 2 * tig);
                    bfr[nt][0] = b2.x; bfr[nt][1] = b2.y;
                } else {
                    const uint32_t* bb = reinterpret_cast<const uint32_t*>(
                        Bs + (cur * 32 + ks + 2 * tig) * BSTRIDE + col);
                    bfr[nt][0] = bb[0];
                    bfr[nt][1] = bb[BSTRIDE];
                }
            }
            #pragma unroll
            for (int mf = 0; mf < 2; mf++)
                #pragma unroll
                for (int nf = 0; nf < 8; nf++)
                    mma_tf32(acc[mf][nf], af[mf], bfr[nf][0], bfr[nf][1]);
        }
        __syncthreads();
    }

    // -------- epilogue --------
    #pragma unroll
    for (int mf = 0; mf < 2; mf++)
    #pragma unroll
    for (int nf = 0; nf < 8; nf++)
    #pragma unroll
    for (int h = 0; h < 2; h++) {
        int m = m0 + wm * 32 + mf * 16 + lm + h * 8;
        int n = n0 + wn * 64 + nf * 8 + ln;
        float v0 = acc[mf][nf][h * 2 + 0];
        float v1 = acc[mf][nf][h * 2 + 1];
        if constexpr (MODE == 0) {
            float h0 = silu_f(v0 + bias[n]);
            float h1 = silu_f(v1 + bias[n + 1]);
            if (n < HIDX)
                *reinterpret_cast<float2*>(g_v + (size_t)m * HIDX + n)
                    = make_float2(tfr(h0), tfr(h1));
            else
                *reinterpret_cast<float2*>(g_gate + (size_t)m * HIDX + (n - HIDX)) = make_float2(h0, h1);
        } else if constexpr (MODE == 1) {
            float h0 = silu_f(v0 + bias[n]);
            float h1 = silu_f(v1 + bias[n + 1]);
            *reinterpret_cast<float2*>(g_qksilu + (size_t)m * QKD + n) = make_float2(h0, h1);
        } else if constexpr (MODE == 2) {
            float a0 = 0.f, a1 = 0.f;
            if (n <= m)     { float s = v0 * (1.f/256.f) + g_biastab[m - n];     s = fmaxf(s, 0.f); a0 = s * s; }
            if (n + 1 <= m) { float s = v1 * (1.f/256.f) + g_biastab[m - n - 1]; s = fmaxf(s, 0.f); a1 = s * s; }
            *reinterpret_cast<float2*>(g_attn + (size_t)bg * GQ * GQ + (size_t)m * GQ + n)
                = make_float2(tfr(a0), tfr(a1));
        } else if constexpr (MODE == 3) {
            *reinterpret_cast<float2*>(g_linkv + (size_t)bg * QKD * HIDX + (size_t)m * HIDX + n)
                = make_float2(v0 * (1.f/256.f), v1 * (1.f/256.f));
        } else if constexpr (MODE == 4) {
            size_t row = (size_t)(bg * GQ + m);
            float2 gt = *reinterpret_cast<const float2*>(g_gate + row * HIDX + n);
            *reinterpret_cast<float2*>(g_act + row * HIDX + n)
                = make_float2(tfr(v0 * gt.x), tfr(v1 * gt.y));
        } else {
            size_t off = (size_t)m * DIMX + n;
            float2 xr = *reinterpret_cast<const float2*>(xres + off);
            *reinterpret_cast<float2*>(out + off)
                = make_float2(v0 + bias[n] + xr.x, v1 + bias[n + 1] + xr.y);
        }
    }
}

// ---------------- host launcher ----------------
extern "C" void kernel_launch(void* const* d_in, const int* in_sizes, int n_in,
                              void* d_out, int out_size) {
    const float* x         = (const float*)d_in[0];
    const float* ln_w      = (const float*)d_in[1];
    const float* ln_b      = (const float*)d_in[2];
    const float* Wh        = (const float*)d_in[3];
    const float* bh        = (const float*)d_in[4];
    const float* Wqk       = (const float*)d_in[5];
    const float* bqk       = (const float*)d_in[6];
    const float* qk_w      = (const float*)d_in[7];
    const float* qk_b      = (const float*)d_in[8];
    const float* rel_table = (const float*)d_in[9];
    const float* Wout      = (const float*)d_in[10];
    const float* bout      = (const float*)d_in[11];
    float* out = (float*)d_out;

    cudaFuncSetAttribute(gemm_kernel<0>, cudaFuncAttributeMaxDynamicSharedMemorySize, SMEMB(0));
    cudaFuncSetAttribute(gemm_kernel<1>, cudaFuncAttributeMaxDynamicSharedMemorySize, SMEMB(1));
    cudaFuncSetAttribute(gemm_kernel<2>, cudaFuncAttributeMaxDynamicSharedMemorySize, SMEMB(2));
    cudaFuncSetAttribute(gemm_kernel<3>, cudaFuncAttributeMaxDynamicSharedMemorySize, SMEMB(3));
    cudaFuncSetAttribute(gemm_kernel<4>, cudaFuncAttributeMaxDynamicSharedMemorySize, SMEMB(4));
    cudaFuncSetAttribute(gemm_kernel<5>, cudaFuncAttributeMaxDynamicSharedMemorySize, SMEMB(5));

    float* WhT_p;  cudaGetSymbolAddress((void**)&WhT_p,  g_WhT);
    float* WqkT_p; cudaGetSymbolAddress((void**)&WqkT_p, g_WqkT);
    float* WoutT_p;cudaGetSymbolAddress((void**)&WoutT_p,g_WoutT);

    prep_kernel<<<1, 256>>>(rel_table);
    transpose_kernel<<<dim3(128, 32), dim3(32, 8)>>>(Wh,   WhT_p,   DIMX, 2 * HIDX);
    transpose_kernel<<<dim3(4, 32),   dim3(32, 8)>>>(Wqk,  WqkT_p,  DIMX, QKD);
    transpose_kernel<<<dim3(32, 64),  dim3(32, 8)>>>(Wout, WoutT_p, HIDX, DIMX);
    ln_kernel<<<NTOK, 256>>>(x, ln_w, ln_b);
    gemm_kernel<0><<<dim3(128, 32, 1), 256, SMEMB(0)>>>(bh, nullptr, nullptr);
    gemm_kernel<1><<<dim3(128, 1, 1),  256, SMEMB(1)>>>(bqk, nullptr, nullptr);
    qkhead_kernel<<<NTOK, 128>>>(qk_w, qk_b);
    gemm_kernel<2><<<dim3(3, 1, 64),  256, SMEMB(2)>>>(nullptr, nullptr, nullptr);
    gemm_kernel<3><<<dim3(1, 16, 64), 256, SMEMB(3)>>>(nullptr, nullptr, nullptr);
    cumsum_kernel<<<4096, 256>>>();
    gemm_kernel<4><<<dim3(2, 16, 64), 256, SMEMB(4)>>>(nullptr, nullptr, nullptr);
    gemm_kernel<5><<<dim3(128, 8, 1), 256, SMEMB(5)>>>(bout, x, out);
}

// round 10
// speedup vs baseline: 1.1635x; 1.0619x over previous
#include <cuda_runtime.h>
#include <cuda_bf16.h>
#include <cstdint>
#include <math.h>

#define DIMX  1024
#define GQ    256
#define QKD   128
#define HIDX  2048
#define NTOK  16384
#define NBG   64

// ---------------- scratch (device globals; no allocation) ----------------
__device__ float g_normed[(size_t)NTOK * DIMX];
__device__ float g_v    [(size_t)NTOK * HIDX];
__device__ float g_gate [(size_t)NTOK * HIDX];
__device__ float g_qksilu[(size_t)NTOK * QKD];
__device__ float g_qq   [(size_t)NTOK * QKD];
__device__ float g_lq   [(size_t)NTOK * QKD];
__device__ float g_qkT  [(size_t)NBG * QKD * GQ];
__device__ float g_lkT  [(size_t)NBG * QKD * GQ];
__device__ float g_attn [(size_t)NBG * GQ * GQ];
__device__ float g_linkv[(size_t)NBG * QKD * HIDX];
__device__ float g_linkvc[(size_t)NBG * QKD * HIDX];
__device__ float g_act  [(size_t)NTOK * HIDX];
__device__ float g_biastab[GQ];
// tf32-pre-rounded, K-major (transposed) weights
__device__ float g_WcatT[(size_t)(2 * HIDX + QKD) * DIMX];  // [4224][1024]: Wh rows then Wqk rows
__device__ float g_WoutT[(size_t)DIMX * HIDX];              // [1024][2048]

// ---------------- small helpers ----------------
__device__ __forceinline__ float silu_f(float x) { return x / (1.0f + expf(-x)); }

__device__ __forceinline__ float tfr(float f) {        // round fp32 -> tf32 (bits in fp32)
    uint32_t r;
    asm("cvt.rna.tf32.f32 %0, %1;" : "=r"(r) : "f"(f));
    return __uint_as_float(r);
}
__device__ __forceinline__ void mma_tf32(float (&d)[4], const uint32_t (&a)[4],
                                         uint32_t b0, uint32_t b1) {
    asm volatile(
        "mma.sync.aligned.m16n8k8.row.col.f32.tf32.tf32.f32 "
        "{%0,%1,%2,%3}, {%4,%5,%6,%7}, {%8,%9}, {%0,%1,%2,%3};\n"
        : "+f"(d[0]), "+f"(d[1]), "+f"(d[2]), "+f"(d[3])
        : "r"(a[0]), "r"(a[1]), "r"(a[2]), "r"(a[3]), "r"(b0), "r"(b1));
}

// ---------------- prep: T5 bias table ----------------
__global__ void prep_kernel(const float* __restrict__ rel_table) {
    int n = threadIdx.x;   // causal distance 0..255
    int bucket;
    if (n < 16) bucket = n;
    else {
        int v = 16 + (int)(logf((float)n / 16.0f) / logf(8.0f) * 16.0f);
        bucket = v < 31 ? v : 31;
    }
    g_biastab[n] = rel_table[bucket] * sqrtf(128.0f);
}

// ---------------- transpose + tf32 round: src[R][C] -> dst[C][R] ----------------
__global__ void transpose_kernel(const float* __restrict__ src, float* __restrict__ dst,
                                 int R, int C) {
    __shared__ float t[32][33];
    int c0 = blockIdx.x * 32, r0 = blockIdx.y * 32;
    int tx = threadIdx.x, ty = threadIdx.y;   // 32 x 8
    #pragma unroll
    for (int j = 0; j < 32; j += 8)
        t[ty + j][tx] = tfr(src[(size_t)(r0 + ty + j) * C + c0 + tx]);
    __syncthreads();
    #pragma unroll
    for (int j = 0; j < 32; j += 8)
        dst[(size_t)(c0 + ty + j) * R + r0 + tx] = t[tx][ty + j];
}

// ---------------- LayerNorm -> fp32 (tf32-rounded) ----------------
__global__ void ln_kernel(const float* __restrict__ x, const float* __restrict__ w,
                          const float* __restrict__ b) {
    int row = blockIdx.x, t = threadIdx.x;   // 256 threads, 4 floats each
    float4 f = reinterpret_cast<const float4*>(x + (size_t)row * DIMX)[t];
    float s  = f.x + f.y + f.z + f.w;
    float s2 = f.x*f.x + f.y*f.y + f.z*f.z + f.w*f.w;
    #pragma unroll
    for (int o = 16; o; o >>= 1) {
        s  += __shfl_xor_sync(0xffffffffu, s,  o);
        s2 += __shfl_xor_sync(0xffffffffu, s2, o);
    }
    __shared__ float ss[8], ss2[8], smu, sinv;
    if ((t & 31) == 0) { ss[t >> 5] = s; ss2[t >> 5] = s2; }
    __syncthreads();
    if (t == 0) {
        float S = 0.f, S2 = 0.f;
        #pragma unroll
        for (int k = 0; k < 8; k++) { S += ss[k]; S2 += ss2[k]; }
        float mu  = S * (1.0f / 1024.0f);
        float var = S2 * (1.0f / 1024.0f) - mu * mu;
        smu = mu; sinv = rsqrtf(var + 1e-5f);
    }
    __syncthreads();
    float mu = smu, inv = sinv;
    float4 wv = reinterpret_cast<const float4*>(w)[t];
    float4 bv = reinterpret_cast<const float4*>(b)[t];
    float4 o;
    o.x = tfr((f.x - mu)*inv*wv.x + bv.x);
    o.y = tfr((f.y - mu)*inv*wv.y + bv.y);
    o.z = tfr((f.z - mu)*inv*wv.z + bv.z);
    o.w = tfr((f.w - mu)*inv*wv.w + bv.w);
    reinterpret_cast<float4*>(g_normed + (size_t)row * DIMX)[t] = o;
}

// ---------------- head expand ----------------
__global__ void qkhead_kernel(const float* __restrict__ qk_w, const float* __restrict__ qk_b) {
    int t = blockIdx.x;        // token
    int d = threadIdx.x;       // 0..127
    float v = g_qksilu[(size_t)t * QKD + d];
    int bg = t >> 8, nl = t & 255;
    g_qq[(size_t)t * QKD + d] = tfr(v * qk_w[d]         + qk_b[d]);
    g_lq[(size_t)t * QKD + d] = tfr(v * qk_w[QKD + d]   + qk_b[QKD + d]);
    g_qkT[(size_t)bg * QKD * GQ + (size_t)d * GQ + nl] = tfr(v * qk_w[2*QKD + d] + qk_b[2*QKD + d]);
    g_lkT[(size_t)bg * QKD * GQ + (size_t)d * GQ + nl] = tfr(v * qk_w[3*QKD + d] + qk_b[3*QKD + d]);
}

// ---------------- exclusive cumsum over groups ----------------
__global__ void cumsum_kernel() {
    int i  = blockIdx.x * 256 + threadIdx.x;
    int b  = i >> 18;
    int de = i & ((1 << 18) - 1);
    float a = 0.f;
    #pragma unroll
    for (int g = 0; g < 16; g++) {
        size_t off = ((size_t)(b * 16 + g) << 18) + de;
        g_linkvc[off] = tfr(a);
        a += g_linkv[off];
    }
}

#define ASTRIDE 40
#define BSTRIDE 132

// ================= weight GEMMs: 128x128 CTA, 64x64 warp tiles, 128 thr ======
// W=0: normed @ WcatT'  M=16384 N=4224 K=1024; n<2048->v(silu), <4096->gate(silu), else qksilu(silu)
// W=1: act @ WoutT'     M=16384 N=1024 K=2048; out = acc + bout + x
#define W_ABUF (128 * ASTRIDE)
#define W_SMEM (4 * W_ABUF * 4)

template<int W>
__global__ void __launch_bounds__(128) wgemm(const float* __restrict__ bias1,
                                             const float* __restrict__ bias2,
                                             const float* __restrict__ xres,
                                             float* __restrict__ out) {
    constexpr int K  = W ? 2048 : 1024;
    constexpr int KT = K / 32;
    const float* A = W ? g_act : g_normed;
    const float* B = W ? g_WoutT : g_WcatT;

    extern __shared__ float smem[];
    float* As = smem;                  // [2][128][ASTRIDE]
    float* Bs = smem + 2 * W_ABUF;     // [2][128][ASTRIDE]
    uint32_t sA = (uint32_t)__cvta_generic_to_shared(As);
    uint32_t sB = (uint32_t)__cvta_generic_to_shared(Bs);

    const int tid = threadIdx.x;
    const int m0 = blockIdx.x * 128, n0 = blockIdx.y * 128;
    const int warp = tid >> 5, lane = tid & 31;
    const int wm = warp >> 1, wn = warp & 1;           // 2x2 warps -> 64x64 each
    const int gid = lane >> 2, tig = lane & 3;
    const int lm = lane >> 2, ln = (lane & 3) << 1;

    float acc[4][8][4];
    #pragma unroll
    for (int a = 0; a < 4; a++)
        #pragma unroll
        for (int b = 0; b < 8; b++)
            #pragma unroll
            for (int c = 0; c < 4; c++) acc[a][b][c] = 0.f;

    auto load_tile = [&](int kt, int buf) {
        int k0 = kt * 32;
        const float* Ab = A + (size_t)m0 * K + k0;
        const float* Bb = B + (size_t)n0 * K + k0;
        #pragma unroll
        for (int it = 0; it < 8; it++) {
            int idx = tid + it * 128;
            int r = idx >> 3, kc = (idx & 7) << 2;
            uint32_t sa = sA + ((buf * 128 + r) * ASTRIDE + kc) * 4;
            asm volatile("cp.async.cg.shared.global [%0], [%1], 16;\n"
                         :: "r"(sa), "l"(Ab + (size_t)r * K + kc));
        }
        #pragma unroll
        for (int it = 0; it < 8; it++) {
            int idx = tid + it * 128;
            int r = idx >> 3, kc = (idx & 7) << 2;
            uint32_t sb = sB + ((buf * 128 + r) * ASTRIDE + kc) * 4;
            asm volatile("cp.async.cg.shared.global [%0], [%1], 16;\n"
                         :: "r"(sb), "l"(Bb + (size_t)r * K + kc));
        }
        asm volatile("cp.async.commit_group;\n");
    };

    load_tile(0, 0);
    for (int kt = 0; kt < KT; kt++) {
        int cur = kt & 1;
        if (kt + 1 < KT) {
            load_tile(kt + 1, cur ^ 1);
            asm volatile("cp.async.wait_group 1;\n");
        } else {
            asm volatile("cp.async.wait_group 0;\n");
        }
        __syncthreads();
        // k-permutation: logical frag slots {tig, tig+4} read physical cols {2tig, 2tig+1}
        #pragma unroll
        for (int ks = 0; ks < 32; ks += 8) {
            uint32_t af[4][4], bfr[8][2];
            #pragma unroll
            for (int mf = 0; mf < 4; mf++) {
                const float* ab = As + (cur * 128 + wm * 64 + mf * 16 + gid) * ASTRIDE + ks + 2 * tig;
                uint2 l0 = *reinterpret_cast<const uint2*>(ab);
                uint2 l1 = *reinterpret_cast<const uint2*>(ab + 8 * ASTRIDE);
                af[mf][0] = l0.x; af[mf][1] = l1.x; af[mf][2] = l0.y; af[mf][3] = l1.y;
            }
            #pragma unroll
            for (int nt = 0; nt < 8; nt++) {
                uint2 b2 = *reinterpret_cast<const uint2*>(
                    Bs + (cur * 128 + wn * 64 + nt * 8 + gid) * ASTRIDE + ks + 2 * tig);
                bfr[nt][0] = b2.x; bfr[nt][1] = b2.y;
            }
            #pragma unroll
            for (int mf = 0; mf < 4; mf++)
                #pragma unroll
                for (int nf = 0; nf < 8; nf++)
                    mma_tf32(acc[mf][nf], af[mf], bfr[nf][0], bfr[nf][1]);
        }
        __syncthreads();
    }

    // -------- epilogue --------
    #pragma unroll
    for (int mf = 0; mf < 4; mf++)
    #pragma unroll
    for (int nf = 0; nf < 8; nf++)
    #pragma unroll
    for (int h = 0; h < 2; h++) {
        int m = m0 + wm * 64 + mf * 16 + lm + h * 8;
        int n = n0 + wn * 64 + nf * 8 + ln;
        float v0 = acc[mf][nf][h * 2 + 0];
        float v1 = acc[mf][nf][h * 2 + 1];
        if constexpr (W == 0) {
            float b0 = (n < 4096) ? bias1[n] : bias2[n - 4096];
            float b1 = (n < 4096) ? bias1[n + 1] : bias2[n - 4095];
            float h0 = silu_f(v0 + b0);
            float h1 = silu_f(v1 + b1);
            if (n < HIDX)
                *reinterpret_cast<float2*>(g_v + (size_t)m * HIDX + n)
                    = make_float2(tfr(h0), tfr(h1));
            else if (n < 2 * HIDX)
                *reinterpret_cast<float2*>(g_gate + (size_t)m * HIDX + (n - HIDX))
                    = make_float2(h0, h1);
            else
                *reinterpret_cast<float2*>(g_qksilu + (size_t)m * QKD + (n - 2 * HIDX))
                    = make_float2(h0, h1);
        } else {
            size_t off = (size_t)m * DIMX + n;
            float2 xr = *reinterpret_cast<const float2*>(xres + off);
            *reinterpret_cast<float2*>(out + off)
                = make_float2(v0 + bias1[n] + xr.x, v1 + bias1[n + 1] + xr.y);
        }
    }
}

// ================= attention GEMMs (modes 2/3/4), unchanged from R9 ==========
// MODE 2: sim = qq@qkT /256 +bias, relu^2, mask   M=256b  N=256  K=128
// MODE 3: linkv = lkT@v /256                      M=128b  N=2048 K=256
// MODE 4: [attn|lq]@[v;linkvc], * gate -> act     M=256b  N=2048 K=384
constexpr int KDIM[5] = {0, 0, 128, 256, 384};

#define A_BUF   (128 * ASTRIDE)
#define B_BUF_N (32 * BSTRIDE)
#define SMEMB_N ((2 * A_BUF + 2 * B_BUF_N) * 4)

template<int MODE>
__device__ __forceinline__ const float* a_ptr(int bg, int m, int k) {
    if constexpr (MODE == 2) return g_qq + ((size_t)bg * GQ + m) * QKD + k;
    else if constexpr (MODE == 3) return g_lkT + (size_t)bg * QKD * GQ + (size_t)m * GQ + k;
    else {
        if (k < GQ) return g_attn + (size_t)bg * GQ * GQ + (size_t)m * GQ + k;
        else        return g_lq + ((size_t)bg * GQ + m) * QKD + (k - GQ);
    }
}
template<int MODE>
__device__ __forceinline__ const float* bnm_ptr(int bg, int k, int n) {
    if constexpr (MODE == 2) return g_qkT + (size_t)bg * QKD * GQ + (size_t)k * GQ + n;
    else if constexpr (MODE == 3) return g_v + ((size_t)bg * GQ + k) * HIDX + n;
    else {
        if (k < GQ) return g_v + ((size_t)bg * GQ + k) * HIDX + n;
        else        return g_linkvc + (size_t)bg * QKD * HIDX + (size_t)(k - GQ) * HIDX + n;
    }
}

template<int MODE>
__global__ void __launch_bounds__(256) gemm_kernel() {
    constexpr int K  = KDIM[MODE];
    constexpr int KT = K / 32;
    extern __shared__ float smem[];
    float* As = smem;                 // [2][128][ASTRIDE]
    float* Bs = smem + 2 * A_BUF;     // [2][32][BSTRIDE]

    const int tid = threadIdx.x;
    int bx = blockIdx.x, by = blockIdx.y;
    if constexpr (MODE == 2) {        // lower-triangular blocks only: (0,0),(1,0),(1,1)
        int t = blockIdx.x;
        bx = (t + 1) >> 1;
        by = t >> 1;
    }
    const int m0 = bx * 128;
    const int n0 = by * 128;
    const int bg = blockIdx.z;
    const int warp = tid >> 5, lane = tid & 31;
    const int wm = warp & 3, wn = warp >> 2;           // 4x2 warps -> 32x64 each
    const int gid = lane >> 2, tig = lane & 3;
    const int lm = lane >> 2, ln = (lane & 3) << 1;

    uint32_t sA = (uint32_t)__cvta_generic_to_shared(As);
    uint32_t sB = (uint32_t)__cvta_generic_to_shared(Bs);

    float acc[2][8][4];
    #pragma unroll
    for (int a = 0; a < 2; a++)
        #pragma unroll
        for (int b = 0; b < 8; b++)
            #pragma unroll
            for (int c = 0; c < 4; c++) acc[a][b][c] = 0.f;

    auto load_tile = [&](int kt, int buf) {
        int k0 = kt * 32;
        #pragma unroll
        for (int it = 0; it < 4; it++) {
            int idx = tid + it * 256;
            int r = idx >> 3, kc = (idx & 7) << 2;
            const float* gp = a_ptr<MODE>(bg, m0 + r, k0 + kc);
            uint32_t sa = sA + ((buf * 128 + r) * ASTRIDE + kc) * 4;
            asm volatile("cp.async.cg.shared.global [%0], [%1], 16;\n" :: "r"(sa), "l"(gp));
        }
        #pragma unroll
        for (int it = 0; it < 4; it++) {
            int idx = tid + it * 256;
            int r = idx >> 5, nc = (idx & 31) << 2;
            const float* gp = bnm_ptr<MODE>(bg, k0 + r, n0 + nc);
            uint32_t sb = sB + ((buf * 32 + r) * BSTRIDE + nc) * 4;
            asm volatile("cp.async.cg.shared.global [%0], [%1], 16;\n" :: "r"(sb), "l"(gp));
        }
        asm volatile("cp.async.commit_group;\n");
    };

    load_tile(0, 0);
    for (int kt = 0; kt < KT; kt++) {
        int cur = kt & 1;
        if (kt + 1 < KT) {
            load_tile(kt + 1, cur ^ 1);
            asm volatile("cp.async.wait_group 1;\n");
        } else {
            asm volatile("cp.async.wait_group 0;\n");
        }
        __syncthreads();
        #pragma unroll
        for (int ks = 0; ks < 32; ks += 8) {
            uint32_t af[2][4], bfr[8][2];
            #pragma unroll
            for (int mf = 0; mf < 2; mf++) {
                const float* ab = As + (cur * 128 + wm * 32 + mf * 16 + gid) * ASTRIDE + ks + 2 * tig;
                uint2 l0 = *reinterpret_cast<const uint2*>(ab);
                uint2 l1 = *reinterpret_cast<const uint2*>(ab + 8 * ASTRIDE);
                af[mf][0] = l0.x; af[mf][1] = l1.x; af[mf][2] = l0.y; af[mf][3] = l1.y;
            }
            #pragma unroll
            for (int nt = 0; nt < 8; nt++) {
                const uint32_t* bb = reinterpret_cast<const uint32_t*>(
                    Bs + (cur * 32 + ks + 2 * tig) * BSTRIDE + wn * 64 + nt * 8 + gid);
                bfr[nt][0] = bb[0];
                bfr[nt][1] = bb[BSTRIDE];
            }
            #pragma unroll
            for (int mf = 0; mf < 2; mf++)
                #pragma unroll
                for (int nf = 0; nf < 8; nf++)
                    mma_tf32(acc[mf][nf], af[mf], bfr[nf][0], bfr[nf][1]);
        }
        __syncthreads();
    }

    #pragma unroll
    for (int mf = 0; mf < 2; mf++)
    #pragma unroll
    for (int nf = 0; nf < 8; nf++)
    #pragma unroll
    for (int h = 0; h < 2; h++) {
        int m = m0 + wm * 32 + mf * 16 + lm + h * 8;
        int n = n0 + wn * 64 + nf * 8 + ln;
        float v0 = acc[mf][nf][h * 2 + 0];
        float v1 = acc[mf][nf][h * 2 + 1];
        if constexpr (MODE == 2) {
            float a0 = 0.f, a1 = 0.f;
            if (n <= m)     { float s = v0 * (1.f/256.f) + g_biastab[m - n];     s = fmaxf(s, 0.f); a0 = s * s; }
            if (n + 1 <= m) { float s = v1 * (1.f/256.f) + g_biastab[m - n - 1]; s = fmaxf(s, 0.f); a1 = s * s; }
            *reinterpret_cast<float2*>(g_attn + (size_t)bg * GQ * GQ + (size_t)m * GQ + n)
                = make_float2(tfr(a0), tfr(a1));
        } else if constexpr (MODE == 3) {
            *reinterpret_cast<float2*>(g_linkv + (size_t)bg * QKD * HIDX + (size_t)m * HIDX + n)
                = make_float2(v0 * (1.f/256.f), v1 * (1.f/256.f));
        } else {
            size_t row = (size_t)(bg * GQ + m);
            float2 gt = *reinterpret_cast<const float2*>(g_gate + row * HIDX + n);
            *reinterpret_cast<float2*>(g_act + row * HIDX + n)
                = make_float2(tfr(v0 * gt.x), tfr(v1 * gt.y));
        }
    }
}

// ---------------- host launcher ----------------
extern "C" void kernel_launch(void* const* d_in, const int* in_sizes, int n_in,
                              void* d_out, int out_size) {
    const float* x         = (const float*)d_in[0];
    const float* ln_w      = (const float*)d_in[1];
    const float* ln_b      = (const float*)d_in[2];
    const float* Wh        = (const float*)d_in[3];
    const float* bh        = (const float*)d_in[4];
    const float* Wqk       = (const float*)d_in[5];
    const float* bqk       = (const float*)d_in[6];
    const float* qk_w      = (const float*)d_in[7];
    const float* qk_b      = (const float*)d_in[8];
    const float* rel_table = (const float*)d_in[9];
    const float* Wout      = (const float*)d_in[10];
    const float* bout      = (const float*)d_in[11];
    float* out = (float*)d_out;

    cudaFuncSetAttribute(wgemm<0>, cudaFuncAttributeMaxDynamicSharedMemorySize, W_SMEM);
    cudaFuncSetAttribute(wgemm<1>, cudaFuncAttributeMaxDynamicSharedMemorySize, W_SMEM);
    cudaFuncSetAttribute(gemm_kernel<2>, cudaFuncAttributeMaxDynamicSharedMemorySize, SMEMB_N);
    cudaFuncSetAttribute(gemm_kernel<3>, cudaFuncAttributeMaxDynamicSharedMemorySize, SMEMB_N);
    cudaFuncSetAttribute(gemm_kernel<4>, cudaFuncAttributeMaxDynamicSharedMemorySize, SMEMB_N);

    float* WcatT_p; cudaGetSymbolAddress((void**)&WcatT_p, g_WcatT);
    float* WoutT_p; cudaGetSymbolAddress((void**)&WoutT_p, g_WoutT);

    prep_kernel<<<1, 256>>>(rel_table);
    transpose_kernel<<<dim3(128, 32), dim3(32, 8)>>>(Wh,   WcatT_p,                DIMX, 2 * HIDX);
    transpose_kernel<<<dim3(4, 32),   dim3(32, 8)>>>(Wqk,  WcatT_p + (size_t)4096 * DIMX, DIMX, QKD);
    transpose_kernel<<<dim3(32, 64),  dim3(32, 8)>>>(Wout, WoutT_p,                HIDX, DIMX);
    ln_kernel<<<NTOK, 256>>>(x, ln_w, ln_b);
    wgemm<0><<<dim3(128, 33), 128, W_SMEM>>>(bh, bqk, nullptr, nullptr);
    qkhead_kernel<<<NTOK, 128>>>(qk_w, qk_b);
    gemm_kernel<2><<<dim3(3, 1, 64),  256, SMEMB_N>>>();
    gemm_kernel<3><<<dim3(1, 16, 64), 256, SMEMB_N>>>();
    cumsum_kernel<<<4096, 256>>>();
    gemm_kernel<4><<<dim3(2, 16, 64), 256, SMEMB_N>>>();
    wgemm<1><<<dim3(128, 8), 128, W_SMEM>>>(bout, nullptr, x, out);
}